// round 1
// baseline (speedup 1.0000x reference)
#include <cuda_runtime.h>
#include <cstdint>
#include <cmath>

#define HIDN 1024
#define EMBD 1024
#define BATCH 256
#define SEQL 128
#define NCLS 32000
#define NG   4096   /* 4*HIDN, gate-interleaved: n = 4*j + g, g in {i,f,c,o} */

#define BM 128
#define BN 64
#define BK 16
#define AS 20   /* padded smem stride for A: (m*20+k) conflict-free mod 32 */
#define BSS 20  /* padded smem stride for B */
#define GS 68   /* epilogue gate-tile stride */

// ---------------- device scratch (no allocations allowed) ----------------
static __device__ float g_Uall[NG * HIDN];             // 16 MB, interleaved U
static __device__ float g_Vall[NG * HIDN];             // 16 MB, interleaved V
static __device__ float g_ball[NG];                    // interleaved gate biases
static __device__ float g_Zin[(size_t)SEQL * BATCH * NG]; // 512 MB precomputed input gates
static __device__ float g_h[2][BATCH * HIDN];          // h ping-pong
static __device__ float g_c[BATCH * HIDN];             // cell state

// ---------------- helpers ----------------
__device__ __forceinline__ float f2tf32(float x) {
    uint32_t r;
    asm("cvt.rna.tf32.f32 %0, %1;" : "=r"(r) : "f"(x));
    return __uint_as_float(r);
}

// ---------------- pack: interleave weights, init state ----------------
__global__ void pack_kernel(const float* __restrict__ Ui, const float* __restrict__ Vi, const float* __restrict__ bi,
                            const float* __restrict__ Uf, const float* __restrict__ Vf, const float* __restrict__ bf,
                            const float* __restrict__ Uc, const float* __restrict__ Vc, const float* __restrict__ bc,
                            const float* __restrict__ Uo, const float* __restrict__ Vo, const float* __restrict__ bo,
                            const float* __restrict__ h0, const float* __restrict__ c0)
{
    int idx = blockIdx.x * blockDim.x + threadIdx.x;
    if (idx >= NG * HIDN) return;
    int n = idx >> 10;
    int k = idx & 1023;
    int j = n >> 2, g = n & 3;
    const float *U, *V, *bb;
    if (g == 0)      { U = Ui; V = Vi; bb = bi; }
    else if (g == 1) { U = Uf; V = Vf; bb = bf; }
    else if (g == 2) { U = Uc; V = Vc; bb = bc; }
    else             { U = Uo; V = Vo; bb = bo; }
    g_Uall[idx] = U[j * HIDN + k];
    g_Vall[idx] = V[j * HIDN + k];
    if (k == 0) g_ball[n] = bb[j];
    if (idx < BATCH * HIDN) { g_h[0][idx] = h0[idx]; g_c[idx] = c0[idx]; }
}

// ---------------- tf32 tensor-core GEMM ----------------
// MODE 0: Zin[t*B+b, :] = gather(emb, X) @ Uall^T + ball          (M=32768, N=4096)
// MODE 1: G = h[t&1] @ Vall^T; fused LSTM epilogue -> h[(t&1)^1], c (M=256, N=4096)
// MODE 2: out = h[0] @ W^T + b                                    (M=256, N=32000)
template <int MODE>
__global__ __launch_bounds__(128)
void gemm_kernel(const float* __restrict__ Bglob,
                 const int*   __restrict__ Xids,
                 const float* __restrict__ embp,
                 const float* __restrict__ biasp,
                 float*       __restrict__ Cout,
                 int t)
{
    const int tid  = threadIdx.x;
    const int lane = tid & 31;
    const int warp = tid >> 5;
    const int wm = (warp >> 1) * 64;   // warp row offset in CTA tile
    const int wn = (warp & 1) * 32;    // warp col offset
    const int ntile = blockIdx.x;
    const int mtile = blockIdx.y;
    const int n0 = ntile * BN;
    const int m0 = mtile * BM;

    __shared__ union SM {
        struct { float A[2][BM * AS]; float B[2][BN * BSS]; } mm;
        float G[BM * GS];
    } sm;

    const float* Bw  = (MODE == 0) ? g_Uall : (MODE == 1) ? g_Vall : Bglob;
    const float* Ain = (MODE == 0) ? (const float*)0 : g_h[t & 1];

    const int kcol  = (tid & 3) * 4;   // 0,4,8,12
    const int ldrow = tid >> 2;        // 0..31

    // per-thread global row pointers
    const float* arp[4];
#pragma unroll
    for (int i = 0; i < 4; i++) {
        int r = m0 + ldrow + 32 * i;
        if (MODE == 0) {
            // row r = t*256 + b ; vocab = X[b, t], X is [256][128]
            int v = Xids[(r & 255) * SEQL + (r >> 8)];
            arp[i] = embp + (size_t)v * EMBD + kcol;
        } else {
            arp[i] = Ain + (size_t)r * HIDN + kcol;
        }
    }
    const float* brp[2];
#pragma unroll
    for (int i = 0; i < 2; i++)
        brp[i] = Bw + (size_t)(n0 + ldrow + 32 * i) * HIDN + kcol;

    float4 areg[4], breg[2];
    float acc[4][4][4];
#pragma unroll
    for (int a = 0; a < 4; a++)
#pragma unroll
        for (int b_ = 0; b_ < 4; b_++)
#pragma unroll
            for (int c_ = 0; c_ < 4; c_++) acc[a][b_][c_] = 0.f;

    // prologue: chunk 0 -> smem buf 0
#pragma unroll
    for (int i = 0; i < 4; i++) areg[i] = *(const float4*)(arp[i]);
#pragma unroll
    for (int i = 0; i < 2; i++) breg[i] = *(const float4*)(brp[i]);
#pragma unroll
    for (int i = 0; i < 4; i++) {
        float4 v = areg[i];
        v.x = f2tf32(v.x); v.y = f2tf32(v.y); v.z = f2tf32(v.z); v.w = f2tf32(v.w);
        *(float4*)&sm.mm.A[0][(ldrow + 32 * i) * AS + kcol] = v;
    }
#pragma unroll
    for (int i = 0; i < 2; i++) {
        float4 v = breg[i];
        v.x = f2tf32(v.x); v.y = f2tf32(v.y); v.z = f2tf32(v.z); v.w = f2tf32(v.w);
        *(float4*)&sm.mm.B[0][(ldrow + 32 * i) * BSS + kcol] = v;
    }
    __syncthreads();

    const int NCH = HIDN / BK; // 64
    for (int kc = 0; kc < NCH; kc++) {
        int cur = kc & 1;
        if (kc + 1 < NCH) {
#pragma unroll
            for (int i = 0; i < 4; i++) areg[i] = *(const float4*)(arp[i] + (kc + 1) * BK);
#pragma unroll
            for (int i = 0; i < 2; i++) breg[i] = *(const float4*)(brp[i] + (kc + 1) * BK);
        }
#pragma unroll
        for (int k8 = 0; k8 < BK; k8 += 8) {
            uint32_t af[4][4], bfr[4][2];
#pragma unroll
            for (int mt = 0; mt < 4; mt++) {
                const float* ap = &sm.mm.A[cur][(wm + mt * 16 + (lane >> 2)) * AS + k8 + (lane & 3)];
                af[mt][0] = __float_as_uint(ap[0]);
                af[mt][1] = __float_as_uint(ap[8 * AS]);
                af[mt][2] = __float_as_uint(ap[4]);
                af[mt][3] = __float_as_uint(ap[8 * AS + 4]);
            }
#pragma unroll
            for (int nt = 0; nt < 4; nt++) {
                const float* bp = &sm.mm.B[cur][(wn + nt * 8 + (lane >> 2)) * BSS + k8 + (lane & 3)];
                bfr[nt][0] = __float_as_uint(bp[0]);
                bfr[nt][1] = __float_as_uint(bp[4]);
            }
#pragma unroll
            for (int mt = 0; mt < 4; mt++)
#pragma unroll
                for (int nt = 0; nt < 4; nt++)
                    asm volatile(
                        "mma.sync.aligned.m16n8k8.row.col.f32.tf32.tf32.f32 "
                        "{%0,%1,%2,%3}, {%4,%5,%6,%7}, {%8,%9}, {%0,%1,%2,%3};"
                        : "+f"(acc[mt][nt][0]), "+f"(acc[mt][nt][1]),
                          "+f"(acc[mt][nt][2]), "+f"(acc[mt][nt][3])
                        : "r"(af[mt][0]), "r"(af[mt][1]), "r"(af[mt][2]), "r"(af[mt][3]),
                          "r"(bfr[nt][0]), "r"(bfr[nt][1]));
        }
        if (kc + 1 < NCH) {
            int nxt = cur ^ 1;
#pragma unroll
            for (int i = 0; i < 4; i++) {
                float4 v = areg[i];
                v.x = f2tf32(v.x); v.y = f2tf32(v.y); v.z = f2tf32(v.z); v.w = f2tf32(v.w);
                *(float4*)&sm.mm.A[nxt][(ldrow + 32 * i) * AS + kcol] = v;
            }
#pragma unroll
            for (int i = 0; i < 2; i++) {
                float4 v = breg[i];
                v.x = f2tf32(v.x); v.y = f2tf32(v.y); v.z = f2tf32(v.z); v.w = f2tf32(v.w);
                *(float4*)&sm.mm.B[nxt][(ldrow + 32 * i) * BSS + kcol] = v;
            }
        }
        __syncthreads();
    }

    if (MODE != 1) {
        // plain epilogue: add bias, store
        float* Cp = (MODE == 0) ? g_Zin : Cout;
        const float* bp = (MODE == 0) ? g_ball : biasp;
        const int ldc = (MODE == 0) ? NG : NCLS;
#pragma unroll
        for (int mt = 0; mt < 4; mt++) {
#pragma unroll
            for (int nt = 0; nt < 4; nt++) {
                int r = m0 + wm + mt * 16 + (lane >> 2);
                int cidx = n0 + wn + nt * 8 + (lane & 3) * 2;
                float2 bv = *(const float2*)&bp[cidx];
                float2 v0; v0.x = acc[mt][nt][0] + bv.x; v0.y = acc[mt][nt][1] + bv.y;
                float2 v1; v1.x = acc[mt][nt][2] + bv.x; v1.y = acc[mt][nt][3] + bv.y;
                *(float2*)&Cp[(size_t)r * ldc + cidx] = v0;
                *(float2*)&Cp[(size_t)(r + 8) * ldc + cidx] = v1;
            }
        }
    } else {
        // fused LSTM epilogue: accum -> smem, add Zin[t], nonlinearities, update c/h
#pragma unroll
        for (int mt = 0; mt < 4; mt++) {
#pragma unroll
            for (int nt = 0; nt < 4; nt++) {
                int lr = wm + mt * 16 + (lane >> 2);
                int lc = wn + nt * 8 + (lane & 3) * 2;
                sm.G[lr * GS + lc]           = acc[mt][nt][0];
                sm.G[lr * GS + lc + 1]       = acc[mt][nt][1];
                sm.G[(lr + 8) * GS + lc]     = acc[mt][nt][2];
                sm.G[(lr + 8) * GS + lc + 1] = acc[mt][nt][3];
            }
        }
        __syncthreads();
        float* hout = g_h[(t & 1) ^ 1];
#pragma unroll
        for (int it = 0; it < 16; it++) {
            int idx = tid + it * 128;         // 0..2047 => (128 rows) x (16 j-groups)
            int lr = idx >> 4, jl = idx & 15;
            int m = m0 + lr;
            int jg = ntile * 16 + jl;
            size_t zb = ((size_t)t * BATCH + m) * NG + n0 + jl * 4;
            float4 z = *(const float4*)&g_Zin[zb];
            float p0 = sm.G[lr * GS + jl * 4 + 0] + z.x;  // i
            float p1 = sm.G[lr * GS + jl * 4 + 1] + z.y;  // f
            float p2 = sm.G[lr * GS + jl * 4 + 2] + z.z;  // c~
            float p3 = sm.G[lr * GS + jl * 4 + 3] + z.w;  // o
            float iv = 1.f / (1.f + expf(-p0));
            float fv = 1.f / (1.f + expf(-p1));
            float gv = tanhf(p2);
            float ov = 1.f / (1.f + expf(-p3));
            int ci = m * HIDN + jg;
            float cn = fv * g_c[ci] + iv * gv;
            g_c[ci] = cn;
            hout[ci] = ov * tanhf(cn);
        }
    }
}

// ---------------- launch ----------------
extern "C" void kernel_launch(void* const* d_in, const int* in_sizes, int n_in,
                              void* d_out, int out_size)
{
    const int*   X   = (const int*)  d_in[0];
    const float* h0  = (const float*)d_in[1];
    const float* c0  = (const float*)d_in[2];
    const float* emb = (const float*)d_in[3];
    const float* Ui  = (const float*)d_in[4];
    const float* Vi  = (const float*)d_in[5];
    const float* bi  = (const float*)d_in[6];
    const float* Uf  = (const float*)d_in[7];
    const float* Vf  = (const float*)d_in[8];
    const float* bf  = (const float*)d_in[9];
    const float* Uc  = (const float*)d_in[10];
    const float* Vc  = (const float*)d_in[11];
    const float* bc  = (const float*)d_in[12];
    const float* Uo  = (const float*)d_in[13];
    const float* Vo  = (const float*)d_in[14];
    const float* bo  = (const float*)d_in[15];
    const float* W   = (const float*)d_in[16];
    const float* b   = (const float*)d_in[17];
    float* out = (float*)d_out;

    // 1) interleave weights (n = 4j+g), copy h0/c0 into state buffers
    pack_kernel<<<(NG * HIDN + 255) / 256, 256>>>(Ui, Vi, bi, Uf, Vf, bf,
                                                  Uc, Vc, bc, Uo, Vo, bo, h0, c0);

    // 2) precompute all input-side gate preactivations (parallel over all timesteps)
    gemm_kernel<0><<<dim3(NG / BN, (SEQL * BATCH) / BM), 128>>>(
        nullptr, X, emb, nullptr, nullptr, 0);

    // 3) 128 serial recurrent steps (GEMM + fused LSTM cell)
    for (int t = 0; t < SEQL; t++)
        gemm_kernel<1><<<dim3(NG / BN, BATCH / BM), 128>>>(
            nullptr, nullptr, nullptr, nullptr, nullptr, t);

    // 4) output projection: h_final (= g_h[0] after 128 steps) @ W^T + b
    gemm_kernel<2><<<dim3(NCLS / BN, BATCH / BM), 128>>>(
        W, nullptr, nullptr, b, out, SEQL /* SEQL&1==0 -> reads g_h[0] */);
}

// round 2
// speedup vs baseline: 1.4752x; 1.4752x over previous
#include <cuda_runtime.h>
#include <cuda_bf16.h>
#include <cstdint>
#include <cmath>

#define HIDN 1024
#define EMBD 1024
#define BATCH 256
#define SEQL 128
#define NCLS 32000
#define NG   4096   /* 4*HIDN, gate-interleaved: n = 4*j + g, g in {i,f,c,o} */

#define BM 128
#define BN 64
#define BK 16
#define AS 20   /* padded smem stride: (m*20+k) conflict-free mod 32 */
#define BSS 20
#define GS 68

// ---------------- device scratch (no allocations allowed) ----------------
static __device__ float    g_Uall[NG * HIDN];               // 16 MB interleaved U (tf32 path)
static __device__ unsigned g_Vb[NG * (HIDN / 2)];           // 8 MB interleaved V as bf16x2
static __device__ float    g_ball[NG];
static __device__ float    g_Zin[(size_t)SEQL * BATCH * NG]; // 512 MB input-side gates
static __device__ float    g_h[2][BATCH * HIDN];            // fp32 h ping-pong (final proj reads this)
static __device__ unsigned g_hb[2][BATCH * (HIDN / 2)];     // bf16x2 h ping-pong (recurrent GEMM reads this)
static __device__ float    g_c[BATCH * HIDN];

// ---------------- helpers ----------------
__device__ __forceinline__ float f2tf32(float x) {
    uint32_t r;
    asm("cvt.rna.tf32.f32 %0, %1;" : "=r"(r) : "f"(x));
    return __uint_as_float(r);
}
__device__ __forceinline__ unsigned pack_bf2(float a, float b) {
    __nv_bfloat162 v = __floats2bfloat162_rn(a, b);
    return *reinterpret_cast<unsigned*>(&v);
}

// ---------------- pack: interleave weights (U fp32, V bf16), init state ----------------
__global__ void pack_kernel(const float* __restrict__ Ui, const float* __restrict__ Vi, const float* __restrict__ bi,
                            const float* __restrict__ Uf, const float* __restrict__ Vf, const float* __restrict__ bf,
                            const float* __restrict__ Uc, const float* __restrict__ Vc, const float* __restrict__ bc,
                            const float* __restrict__ Uo, const float* __restrict__ Vo, const float* __restrict__ bo,
                            const float* __restrict__ h0, const float* __restrict__ c0)
{
    int idx = blockIdx.x * blockDim.x + threadIdx.x;
    if (idx >= NG * HIDN) return;
    int n = idx >> 10;
    int k = idx & 1023;
    int j = n >> 2, g = n & 3;
    const float *U, *V, *bb;
    if (g == 0)      { U = Ui; V = Vi; bb = bi; }
    else if (g == 1) { U = Uf; V = Vf; bb = bf; }
    else if (g == 2) { U = Uc; V = Vc; bb = bc; }
    else             { U = Uo; V = Vo; bb = bo; }
    g_Uall[idx] = U[j * HIDN + k];
    if ((k & 1) == 0)
        g_Vb[n * (HIDN / 2) + (k >> 1)] = pack_bf2(V[j * HIDN + k], V[j * HIDN + k + 1]);
    if (k == 0) g_ball[n] = bb[j];
    if (idx < BATCH * HIDN) { g_h[0][idx] = h0[idx]; g_c[idx] = c0[idx]; }
    if (idx < BATCH * (HIDN / 2)) g_hb[0][idx] = pack_bf2(h0[2 * idx], h0[2 * idx + 1]);
}

// ---------------- tf32 GEMM (MODE 0: input gates, MODE 2: output projection) ----------------
template <int MODE>
__global__ __launch_bounds__(128)
void gemm_kernel(const float* __restrict__ Bglob,
                 const int*   __restrict__ Xids,
                 const float* __restrict__ embp,
                 const float* __restrict__ biasp,
                 float*       __restrict__ Cout,
                 int t)
{
    const int tid  = threadIdx.x;
    const int lane = tid & 31;
    const int warp = tid >> 5;
    const int wm = (warp >> 1) * 64;
    const int wn = (warp & 1) * 32;
    const int n0 = blockIdx.x * BN;
    const int m0 = blockIdx.y * BM;

    __shared__ struct { float A[2][BM * AS]; float B[2][BN * BSS]; } sm;

    const float* Bw  = (MODE == 0) ? g_Uall : Bglob;
    const float* Ain = (MODE == 0) ? (const float*)0 : g_h[t & 1];

    const int kcol  = (tid & 3) * 4;
    const int ldrow = tid >> 2;

    const float* arp[4];
#pragma unroll
    for (int i = 0; i < 4; i++) {
        int r = m0 + ldrow + 32 * i;
        if (MODE == 0) {
            int v = Xids[(r & 255) * SEQL + (r >> 8)];
            arp[i] = embp + (size_t)v * EMBD + kcol;
        } else {
            arp[i] = Ain + (size_t)r * HIDN + kcol;
        }
    }
    const float* brp[2];
#pragma unroll
    for (int i = 0; i < 2; i++)
        brp[i] = Bw + (size_t)(n0 + ldrow + 32 * i) * HIDN + kcol;

    float4 areg[4], breg[2];
    float acc[4][4][4];
#pragma unroll
    for (int a = 0; a < 4; a++)
#pragma unroll
        for (int b_ = 0; b_ < 4; b_++)
#pragma unroll
            for (int c_ = 0; c_ < 4; c_++) acc[a][b_][c_] = 0.f;

#pragma unroll
    for (int i = 0; i < 4; i++) areg[i] = *(const float4*)(arp[i]);
#pragma unroll
    for (int i = 0; i < 2; i++) breg[i] = *(const float4*)(brp[i]);
#pragma unroll
    for (int i = 0; i < 4; i++) {
        float4 v = areg[i];
        v.x = f2tf32(v.x); v.y = f2tf32(v.y); v.z = f2tf32(v.z); v.w = f2tf32(v.w);
        *(float4*)&sm.A[0][(ldrow + 32 * i) * AS + kcol] = v;
    }
#pragma unroll
    for (int i = 0; i < 2; i++) {
        float4 v = breg[i];
        v.x = f2tf32(v.x); v.y = f2tf32(v.y); v.z = f2tf32(v.z); v.w = f2tf32(v.w);
        *(float4*)&sm.B[0][(ldrow + 32 * i) * BSS + kcol] = v;
    }
    __syncthreads();

    const int NCH = HIDN / BK;
    for (int kc = 0; kc < NCH; kc++) {
        int cur = kc & 1;
        if (kc + 1 < NCH) {
#pragma unroll
            for (int i = 0; i < 4; i++) areg[i] = *(const float4*)(arp[i] + (kc + 1) * BK);
#pragma unroll
            for (int i = 0; i < 2; i++) breg[i] = *(const float4*)(brp[i] + (kc + 1) * BK);
        }
#pragma unroll
        for (int k8 = 0; k8 < BK; k8 += 8) {
            uint32_t af[4][4], bfr[4][2];
#pragma unroll
            for (int mt = 0; mt < 4; mt++) {
                const float* ap = &sm.A[cur][(wm + mt * 16 + (lane >> 2)) * AS + k8 + (lane & 3)];
                af[mt][0] = __float_as_uint(ap[0]);
                af[mt][1] = __float_as_uint(ap[8 * AS]);
                af[mt][2] = __float_as_uint(ap[4]);
                af[mt][3] = __float_as_uint(ap[8 * AS + 4]);
            }
#pragma unroll
            for (int nt = 0; nt < 4; nt++) {
                const float* bp = &sm.B[cur][(wn + nt * 8 + (lane >> 2)) * BSS + k8 + (lane & 3)];
                bfr[nt][0] = __float_as_uint(bp[0]);
                bfr[nt][1] = __float_as_uint(bp[4]);
            }
#pragma unroll
            for (int mt = 0; mt < 4; mt++)
#pragma unroll
                for (int nt = 0; nt < 4; nt++)
                    asm volatile(
                        "mma.sync.aligned.m16n8k8.row.col.f32.tf32.tf32.f32 "
                        "{%0,%1,%2,%3}, {%4,%5,%6,%7}, {%8,%9}, {%0,%1,%2,%3};"
                        : "+f"(acc[mt][nt][0]), "+f"(acc[mt][nt][1]),
                          "+f"(acc[mt][nt][2]), "+f"(acc[mt][nt][3])
                        : "r"(af[mt][0]), "r"(af[mt][1]), "r"(af[mt][2]), "r"(af[mt][3]),
                          "r"(bfr[nt][0]), "r"(bfr[nt][1]));
        }
        if (kc + 1 < NCH) {
            int nxt = cur ^ 1;
#pragma unroll
            for (int i = 0; i < 4; i++) {
                float4 v = areg[i];
                v.x = f2tf32(v.x); v.y = f2tf32(v.y); v.z = f2tf32(v.z); v.w = f2tf32(v.w);
                *(float4*)&sm.A[nxt][(ldrow + 32 * i) * AS + kcol] = v;
            }
#pragma unroll
            for (int i = 0; i < 2; i++) {
                float4 v = breg[i];
                v.x = f2tf32(v.x); v.y = f2tf32(v.y); v.z = f2tf32(v.z); v.w = f2tf32(v.w);
                *(float4*)&sm.B[nxt][(ldrow + 32 * i) * BSS + kcol] = v;
            }
        }
        __syncthreads();
    }

    float* Cp = (MODE == 0) ? g_Zin : Cout;
    const float* bp = (MODE == 0) ? g_ball : biasp;
    const int ldc = (MODE == 0) ? NG : NCLS;
#pragma unroll
    for (int mt = 0; mt < 4; mt++) {
#pragma unroll
        for (int nt = 0; nt < 4; nt++) {
            int r = m0 + wm + mt * 16 + (lane >> 2);
            int cidx = n0 + wn + nt * 8 + (lane & 3) * 2;
            float2 bv = *(const float2*)&bp[cidx];
            float2 v0; v0.x = acc[mt][nt][0] + bv.x; v0.y = acc[mt][nt][1] + bv.y;
            float2 v1; v1.x = acc[mt][nt][2] + bv.x; v1.y = acc[mt][nt][3] + bv.y;
            *(float2*)&Cp[(size_t)r * ldc + cidx] = v0;
            *(float2*)&Cp[(size_t)(r + 8) * ldc + cidx] = v1;
        }
    }
}

// ---------------- bf16 recurrent step: G = h @ Vall^T, fused LSTM cell ----------------
// grid (64, 2), 256 threads (8 warps, warp tile 32x32), K in half2 units: 512
__global__ __launch_bounds__(256)
void lstm_step_kernel(int t)
{
    const int tid  = threadIdx.x;
    const int lane = tid & 31;
    const int warp = tid >> 5;          // 0..7
    const int wm = (warp >> 1) * 32;    // 4 m-warps * 32 rows
    const int wn = (warp & 1) * 32;     // 2 n-warps * 32 cols
    const int ntile = blockIdx.x;       // 0..63
    const int mtile = blockIdx.y;       // 0..1
    const int n0 = ntile * 64;
    const int m0 = mtile * 128;

    __shared__ union SM {
        struct { unsigned A[2][128 * 20]; unsigned B[2][64 * 20]; } mm;
        float G[128 * GS];
    } sm;

    const unsigned* Ain = g_hb[t & 1];
    const int kcol  = (tid & 3) * 4;    // half2-unit col within 16-wide chunk
    const int ldrow = tid >> 2;         // 0..63

    const unsigned* arp0 = Ain + (size_t)(m0 + ldrow) * 512 + kcol;
    const unsigned* arp1 = Ain + (size_t)(m0 + ldrow + 64) * 512 + kcol;
    const unsigned* brp  = g_Vb + (size_t)(n0 + ldrow) * 512 + kcol;

    uint4 areg0, areg1, breg;
    float acc[2][4][4];
#pragma unroll
    for (int a = 0; a < 2; a++)
#pragma unroll
        for (int b_ = 0; b_ < 4; b_++)
#pragma unroll
            for (int c_ = 0; c_ < 4; c_++) acc[a][b_][c_] = 0.f;

    areg0 = *(const uint4*)arp0;
    areg1 = *(const uint4*)arp1;
    breg  = *(const uint4*)brp;
    *(uint4*)&sm.mm.A[0][ldrow * 20 + kcol]        = areg0;
    *(uint4*)&sm.mm.A[0][(ldrow + 64) * 20 + kcol] = areg1;
    *(uint4*)&sm.mm.B[0][ldrow * 20 + kcol]        = breg;
    __syncthreads();

    const int NCH = 32;   // 512 half2 / 16 per chunk
    for (int kc = 0; kc < NCH; kc++) {
        int cur = kc & 1;
        if (kc + 1 < NCH) {
            areg0 = *(const uint4*)(arp0 + (kc + 1) * 16);
            areg1 = *(const uint4*)(arp1 + (kc + 1) * 16);
            breg  = *(const uint4*)(brp  + (kc + 1) * 16);
        }
#pragma unroll
        for (int ks = 0; ks < 2; ks++) {
            unsigned af[2][4], bfr[4][2];
#pragma unroll
            for (int mt = 0; mt < 2; mt++) {
                const unsigned* ap = &sm.mm.A[cur][(wm + mt * 16 + (lane >> 2)) * 20 + ks * 8 + (lane & 3)];
                af[mt][0] = ap[0];
                af[mt][1] = ap[8 * 20];
                af[mt][2] = ap[4];
                af[mt][3] = ap[8 * 20 + 4];
            }
#pragma unroll
            for (int nt = 0; nt < 4; nt++) {
                const unsigned* bp = &sm.mm.B[cur][(wn + nt * 8 + (lane >> 2)) * 20 + ks * 8 + (lane & 3)];
                bfr[nt][0] = bp[0];
                bfr[nt][1] = bp[4];
            }
#pragma unroll
            for (int mt = 0; mt < 2; mt++)
#pragma unroll
                for (int nt = 0; nt < 4; nt++)
                    asm volatile(
                        "mma.sync.aligned.m16n8k16.row.col.f32.bf16.bf16.f32 "
                        "{%0,%1,%2,%3}, {%4,%5,%6,%7}, {%8,%9}, {%0,%1,%2,%3};"
                        : "+f"(acc[mt][nt][0]), "+f"(acc[mt][nt][1]),
                          "+f"(acc[mt][nt][2]), "+f"(acc[mt][nt][3])
                        : "r"(af[mt][0]), "r"(af[mt][1]), "r"(af[mt][2]), "r"(af[mt][3]),
                          "r"(bfr[nt][0]), "r"(bfr[nt][1]));
        }
        if (kc + 1 < NCH) {
            int nxt = cur ^ 1;
            *(uint4*)&sm.mm.A[nxt][ldrow * 20 + kcol]        = areg0;
            *(uint4*)&sm.mm.A[nxt][(ldrow + 64) * 20 + kcol] = areg1;
            *(uint4*)&sm.mm.B[nxt][ldrow * 20 + kcol]        = breg;
        }
        __syncthreads();
    }

    // accum -> smem gate tile
#pragma unroll
    for (int mt = 0; mt < 2; mt++) {
#pragma unroll
        for (int nt = 0; nt < 4; nt++) {
            int lr = wm + mt * 16 + (lane >> 2);
            int lc = wn + nt * 8 + (lane & 3) * 2;
            sm.G[lr * GS + lc]           = acc[mt][nt][0];
            sm.G[lr * GS + lc + 1]       = acc[mt][nt][1];
            sm.G[(lr + 8) * GS + lc]     = acc[mt][nt][2];
            sm.G[(lr + 8) * GS + lc + 1] = acc[mt][nt][3];
        }
    }
    __syncthreads();

    // fused LSTM cell: 128 rows x 8 j-pairs per CTA, 4 items per thread
    unsigned* hbout = g_hb[(t & 1) ^ 1];
    float*    hfout = g_h[(t & 1) ^ 1];
#pragma unroll
    for (int it = 0; it < 4; it++) {
        int idx = tid + it * 256;        // 0..1023
        int lr = idx >> 3;               // row 0..127
        int jp = idx & 7;                // j-pair 0..7
        int m = m0 + lr;
        size_t zb = ((size_t)t * BATCH + m) * NG + n0 + jp * 8;
        float4 z0 = *(const float4*)&g_Zin[zb];
        float4 z1 = *(const float4*)&g_Zin[zb + 4];
        const float* Gp = &sm.G[lr * GS + jp * 8];

        float i0 = 1.f / (1.f + expf(-(Gp[0] + z0.x)));
        float f0 = 1.f / (1.f + expf(-(Gp[1] + z0.y)));
        float g0 = tanhf(Gp[2] + z0.z);
        float o0 = 1.f / (1.f + expf(-(Gp[3] + z0.w)));
        float i1 = 1.f / (1.f + expf(-(Gp[4] + z1.x)));
        float f1 = 1.f / (1.f + expf(-(Gp[5] + z1.y)));
        float g1 = tanhf(Gp[6] + z1.z);
        float o1 = 1.f / (1.f + expf(-(Gp[7] + z1.w)));

        int ci = m * HIDN + ntile * 16 + jp * 2;
        float2 cold = *(const float2*)&g_c[ci];
        float cn0 = f0 * cold.x + i0 * g0;
        float cn1 = f1 * cold.y + i1 * g1;
        float2 cnew; cnew.x = cn0; cnew.y = cn1;
        *(float2*)&g_c[ci] = cnew;

        float h0v = o0 * tanhf(cn0);
        float h1v = o1 * tanhf(cn1);
        float2 hf; hf.x = h0v; hf.y = h1v;
        *(float2*)&hfout[ci] = hf;
        hbout[m * 512 + ntile * 8 + jp] = pack_bf2(h0v, h1v);
    }
}

// ---------------- launch ----------------
extern "C" void kernel_launch(void* const* d_in, const int* in_sizes, int n_in,
                              void* d_out, int out_size)
{
    const int*   X   = (const int*)  d_in[0];
    const float* h0  = (const float*)d_in[1];
    const float* c0  = (const float*)d_in[2];
    const float* emb = (const float*)d_in[3];
    const float* Ui  = (const float*)d_in[4];
    const float* Vi  = (const float*)d_in[5];
    const float* bi  = (const float*)d_in[6];
    const float* Uf  = (const float*)d_in[7];
    const float* Vf  = (const float*)d_in[8];
    const float* bf  = (const float*)d_in[9];
    const float* Uc  = (const float*)d_in[10];
    const float* Vc  = (const float*)d_in[11];
    const float* bc  = (const float*)d_in[12];
    const float* Uo  = (const float*)d_in[13];
    const float* Vo  = (const float*)d_in[14];
    const float* bo  = (const float*)d_in[15];
    const float* W   = (const float*)d_in[16];
    const float* b   = (const float*)d_in[17];
    float* out = (float*)d_out;

    // 1) interleave weights (U fp32, V bf16), copy h0/c0
    pack_kernel<<<(NG * HIDN + 255) / 256, 256>>>(Ui, Vi, bi, Uf, Vf, bf,
                                                  Uc, Vc, bc, Uo, Vo, bo, h0, c0);

    // 2) all input-side gate preactivations (tf32, parallel over timesteps)
    gemm_kernel<0><<<dim3(NG / BN, (SEQL * BATCH) / BM), 128>>>(
        nullptr, X, emb, nullptr, nullptr, 0);

    // 3) 128 serial recurrent steps (bf16 GEMM + fused LSTM cell)
    for (int t = 0; t < SEQL; t++)
        lstm_step_kernel<<<dim3(64, 2), 256>>>(t);

    // 4) output projection: h_final (fp32, in g_h[0]) @ W^T + b
    gemm_kernel<2><<<dim3(NCLS / BN, BATCH / BM), 128>>>(
        W, nullptr, nullptr, b, out, SEQL);
}

// round 3
// speedup vs baseline: 1.8323x; 1.2421x over previous
#include <cuda_runtime.h>
#include <cuda_bf16.h>
#include <cstdint>
#include <cmath>

#define HIDN 1024
#define EMBD 1024
#define BATCH 256
#define SEQL 128
#define NCLS 32000
#define NG   4096   /* 4*HIDN, gate-interleaved: n = 4*j + g, g in {i,f,c,o} */

#define BM 128
#define BN 64
#define BK 16
#define AS 20   /* padded smem stride: conflict-free */
#define BSS 20
#define GS 68
#define VSTR 516 /* resident-V smem row stride (half2 units), 516 % 32 == 4 -> conflict-free */

#define NCTA 128
#define PTHREADS 256

// ---------------- device scratch (no allocations allowed) ----------------
static __device__ float    g_Uall[NG * HIDN];               // 16 MB interleaved U (tf32 path)
static __device__ unsigned g_Vb[NG * (HIDN / 2)];           // 8 MB interleaved V as bf16x2
static __device__ float    g_ball[NG];
static __device__ float    g_Zin[(size_t)SEQL * BATCH * NG]; // 512 MB input-side gates
static __device__ float    g_h[2][BATCH * HIDN];            // fp32 h (final proj reads [0])
static __device__ unsigned g_hb[2][BATCH * (HIDN / 2)];     // bf16x2 h ping-pong
static __device__ float    g_c[BATCH * HIDN];
static __device__ unsigned g_bar;                           // persistent-kernel grid barrier

// ---------------- helpers ----------------
__device__ __forceinline__ float f2tf32(float x) {
    uint32_t r;
    asm("cvt.rna.tf32.f32 %0, %1;" : "=r"(r) : "f"(x));
    return __uint_as_float(r);
}
__device__ __forceinline__ unsigned pack_bf2(float a, float b) {
    __nv_bfloat162 v = __floats2bfloat162_rn(a, b);
    return *reinterpret_cast<unsigned*>(&v);
}
__device__ __forceinline__ float fsig(float x) {
    return __fdividef(1.f, 1.f + __expf(-x));
}

// ---------------- pack: interleave weights (U fp32, V bf16), init state ----------------
__global__ void pack_kernel(const float* __restrict__ Ui, const float* __restrict__ Vi, const float* __restrict__ bi,
                            const float* __restrict__ Uf, const float* __restrict__ Vf, const float* __restrict__ bf,
                            const float* __restrict__ Uc, const float* __restrict__ Vc, const float* __restrict__ bc,
                            const float* __restrict__ Uo, const float* __restrict__ Vo, const float* __restrict__ bo,
                            const float* __restrict__ h0, const float* __restrict__ c0)
{
    int idx = blockIdx.x * blockDim.x + threadIdx.x;
    if (idx >= NG * HIDN) return;
    if (idx == 0) g_bar = 0u;
    int n = idx >> 10;
    int k = idx & 1023;
    int j = n >> 2, g = n & 3;
    const float *U, *V, *bb;
    if (g == 0)      { U = Ui; V = Vi; bb = bi; }
    else if (g == 1) { U = Uf; V = Vf; bb = bf; }
    else if (g == 2) { U = Uc; V = Vc; bb = bc; }
    else             { U = Uo; V = Vo; bb = bo; }
    g_Uall[idx] = U[j * HIDN + k];
    if ((k & 1) == 0)
        g_Vb[n * (HIDN / 2) + (k >> 1)] = pack_bf2(V[j * HIDN + k], V[j * HIDN + k + 1]);
    if (k == 0) g_ball[n] = bb[j];
    if (idx < BATCH * HIDN) { g_h[0][idx] = h0[idx]; g_c[idx] = c0[idx]; }
    if (idx < BATCH * (HIDN / 2)) g_hb[0][idx] = pack_bf2(h0[2 * idx], h0[2 * idx + 1]);
}

// ---------------- tf32 GEMM (MODE 0: input gates, MODE 2: output projection) ----------------
template <int MODE>
__global__ __launch_bounds__(128)
void gemm_kernel(const float* __restrict__ Bglob,
                 const int*   __restrict__ Xids,
                 const float* __restrict__ embp,
                 const float* __restrict__ biasp,
                 float*       __restrict__ Cout,
                 int t)
{
    const int tid  = threadIdx.x;
    const int lane = tid & 31;
    const int warp = tid >> 5;
    const int wm = (warp >> 1) * 64;
    const int wn = (warp & 1) * 32;
    const int n0 = blockIdx.x * BN;
    const int m0 = blockIdx.y * BM;

    __shared__ struct { float A[2][BM * AS]; float B[2][BN * BSS]; } sm;

    const float* Bw  = (MODE == 0) ? g_Uall : Bglob;
    const float* Ain = (MODE == 0) ? (const float*)0 : g_h[t & 1];

    const int kcol  = (tid & 3) * 4;
    const int ldrow = tid >> 2;

    const float* arp[4];
#pragma unroll
    for (int i = 0; i < 4; i++) {
        int r = m0 + ldrow + 32 * i;
        if (MODE == 0) {
            int v = Xids[(r & 255) * SEQL + (r >> 8)];
            arp[i] = embp + (size_t)v * EMBD + kcol;
        } else {
            arp[i] = Ain + (size_t)r * HIDN + kcol;
        }
    }
    const float* brp[2];
#pragma unroll
    for (int i = 0; i < 2; i++)
        brp[i] = Bw + (size_t)(n0 + ldrow + 32 * i) * HIDN + kcol;

    float4 areg[4], breg[2];
    float acc[4][4][4];
#pragma unroll
    for (int a = 0; a < 4; a++)
#pragma unroll
        for (int b_ = 0; b_ < 4; b_++)
#pragma unroll
            for (int c_ = 0; c_ < 4; c_++) acc[a][b_][c_] = 0.f;

#pragma unroll
    for (int i = 0; i < 4; i++) areg[i] = *(const float4*)(arp[i]);
#pragma unroll
    for (int i = 0; i < 2; i++) breg[i] = *(const float4*)(brp[i]);
#pragma unroll
    for (int i = 0; i < 4; i++) {
        float4 v = areg[i];
        v.x = f2tf32(v.x); v.y = f2tf32(v.y); v.z = f2tf32(v.z); v.w = f2tf32(v.w);
        *(float4*)&sm.A[0][(ldrow + 32 * i) * AS + kcol] = v;
    }
#pragma unroll
    for (int i = 0; i < 2; i++) {
        float4 v = breg[i];
        v.x = f2tf32(v.x); v.y = f2tf32(v.y); v.z = f2tf32(v.z); v.w = f2tf32(v.w);
        *(float4*)&sm.B[0][(ldrow + 32 * i) * BSS + kcol] = v;
    }
    __syncthreads();

    const int NCH = HIDN / BK;
    for (int kc = 0; kc < NCH; kc++) {
        int cur = kc & 1;
        if (kc + 1 < NCH) {
#pragma unroll
            for (int i = 0; i < 4; i++) areg[i] = *(const float4*)(arp[i] + (kc + 1) * BK);
#pragma unroll
            for (int i = 0; i < 2; i++) breg[i] = *(const float4*)(brp[i] + (kc + 1) * BK);
        }
#pragma unroll
        for (int k8 = 0; k8 < BK; k8 += 8) {
            uint32_t af[4][4], bfr[4][2];
#pragma unroll
            for (int mt = 0; mt < 4; mt++) {
                const float* ap = &sm.A[cur][(wm + mt * 16 + (lane >> 2)) * AS + k8 + (lane & 3)];
                af[mt][0] = __float_as_uint(ap[0]);
                af[mt][1] = __float_as_uint(ap[8 * AS]);
                af[mt][2] = __float_as_uint(ap[4]);
                af[mt][3] = __float_as_uint(ap[8 * AS + 4]);
            }
#pragma unroll
            for (int nt = 0; nt < 4; nt++) {
                const float* bp = &sm.B[cur][(wn + nt * 8 + (lane >> 2)) * BSS + k8 + (lane & 3)];
                bfr[nt][0] = __float_as_uint(bp[0]);
                bfr[nt][1] = __float_as_uint(bp[4]);
            }
#pragma unroll
            for (int mt = 0; mt < 4; mt++)
#pragma unroll
                for (int nt = 0; nt < 4; nt++)
                    asm volatile(
                        "mma.sync.aligned.m16n8k8.row.col.f32.tf32.tf32.f32 "
                        "{%0,%1,%2,%3}, {%4,%5,%6,%7}, {%8,%9}, {%0,%1,%2,%3};"
                        : "+f"(acc[mt][nt][0]), "+f"(acc[mt][nt][1]),
                          "+f"(acc[mt][nt][2]), "+f"(acc[mt][nt][3])
                        : "r"(af[mt][0]), "r"(af[mt][1]), "r"(af[mt][2]), "r"(af[mt][3]),
                          "r"(bfr[nt][0]), "r"(bfr[nt][1]));
        }
        if (kc + 1 < NCH) {
            int nxt = cur ^ 1;
#pragma unroll
            for (int i = 0; i < 4; i++) {
                float4 v = areg[i];
                v.x = f2tf32(v.x); v.y = f2tf32(v.y); v.z = f2tf32(v.z); v.w = f2tf32(v.w);
                *(float4*)&sm.A[nxt][(ldrow + 32 * i) * AS + kcol] = v;
            }
#pragma unroll
            for (int i = 0; i < 2; i++) {
                float4 v = breg[i];
                v.x = f2tf32(v.x); v.y = f2tf32(v.y); v.z = f2tf32(v.z); v.w = f2tf32(v.w);
                *(float4*)&sm.B[nxt][(ldrow + 32 * i) * BSS + kcol] = v;
            }
        }
        __syncthreads();
    }

    float* Cp = (MODE == 0) ? g_Zin : Cout;
    const float* bp = (MODE == 0) ? g_ball : biasp;
    const int ldc = (MODE == 0) ? NG : NCLS;
#pragma unroll
    for (int mt = 0; mt < 4; mt++) {
#pragma unroll
        for (int nt = 0; nt < 4; nt++) {
            int r = m0 + wm + mt * 16 + (lane >> 2);
            int cidx = n0 + wn + nt * 8 + (lane & 3) * 2;
            float2 bv = *(const float2*)&bp[cidx];
            float2 v0; v0.x = acc[mt][nt][0] + bv.x; v0.y = acc[mt][nt][1] + bv.y;
            float2 v1; v1.x = acc[mt][nt][2] + bv.x; v1.y = acc[mt][nt][3] + bv.y;
            *(float2*)&Cp[(size_t)r * ldc + cidx] = v0;
            *(float2*)&Cp[(size_t)(r + 8) * ldc + cidx] = v1;
        }
    }
}

// ---------------- persistent recurrent kernel: all 128 steps in one launch ----------------
// 128 CTAs (1/SM, all co-resident), 256 threads. Each CTA: V slice [64 gate cols x 1024 k]
// resident in SMEM for the whole kernel; c slice resident in registers; h streamed via L2;
// steps separated by a global arrive/spin barrier.
#define SMEM_V_BYTES   (64 * VSTR * 4)
#define SMEM_TAIL      (BM * GS * 4)                 /* G tile (34816 B) > A stage (20480 B) */
#define SMEM_P_BYTES   (SMEM_V_BYTES + SMEM_TAIL)    /* 166912 B */

__global__ __launch_bounds__(PTHREADS, 1)
void lstm_persistent_kernel()
{
    extern __shared__ unsigned smem[];
    unsigned* smV = smem;                          // 64 x VSTR half2
    unsigned* smA = smem + 64 * VSTR;              // 2 x (128 x 20) staging
    float*    smG = (float*)(smem + 64 * VSTR);    // union with smA (epilogue only)

    const int tid  = threadIdx.x;
    const int lane = tid & 31;
    const int warp = tid >> 5;          // 0..7
    const int wm = (warp >> 1) * 32;    // 4 m-warps x 32 rows
    const int wn = (warp & 1) * 32;     // 2 n-warps x 32 cols
    const int bid = blockIdx.x;
    const int m0  = (bid & 1) * 128;
    const int nsl = bid >> 1;           // 0..63
    const int n0  = nsl * 64;

    // one-time: load resident V slice [64][512] half2 -> stride VSTR
    for (int i = tid; i < 64 * 128; i += PTHREADS) {
        int n = i >> 7, k4 = (i & 127) * 4;
        *(uint4*)&smV[n * VSTR + k4] = *(const uint4*)&g_Vb[(size_t)(n0 + n) * 512 + k4];
    }

    // one-time: pull private c slice into registers
    float creg[4][2];
#pragma unroll
    for (int it = 0; it < 4; it++) {
        int idx = tid + it * PTHREADS;
        int lr = idx >> 3, jp = idx & 7;
        float2 cv = *(const float2*)&g_c[(m0 + lr) * HIDN + nsl * 16 + jp * 2];
        creg[it][0] = cv.x; creg[it][1] = cv.y;
    }

    const int kcol  = (tid & 3) * 4;
    const int ldrow = tid >> 2;         // 0..63
    __syncthreads();

    for (int t = 0; t < SEQL; t++) {
        const unsigned* hin = g_hb[t & 1];
        const unsigned* arp0 = hin + (size_t)(m0 + ldrow) * 512 + kcol;
        const unsigned* arp1 = hin + (size_t)(m0 + ldrow + 64) * 512 + kcol;

        float acc[2][4][4];
#pragma unroll
        for (int a = 0; a < 2; a++)
#pragma unroll
            for (int b_ = 0; b_ < 4; b_++)
#pragma unroll
                for (int c_ = 0; c_ < 4; c_++) acc[a][b_][c_] = 0.f;

        uint4 a0 = *(const uint4*)arp0;
        uint4 a1 = *(const uint4*)arp1;
        *(uint4*)&smA[ldrow * 20 + kcol]        = a0;
        *(uint4*)&smA[(ldrow + 64) * 20 + kcol] = a1;
        __syncthreads();

        for (int kc = 0; kc < 32; kc++) {
            const int cur = kc & 1;
            if (kc + 1 < 32) {
                a0 = *(const uint4*)(arp0 + (kc + 1) * 16);
                a1 = *(const uint4*)(arp1 + (kc + 1) * 16);
            }
            const unsigned* As = smA + cur * (128 * 20);
#pragma unroll
            for (int ks = 0; ks < 2; ks++) {
                unsigned af[2][4], bfr[4][2];
#pragma unroll
                for (int mt = 0; mt < 2; mt++) {
                    const unsigned* ap = &As[(wm + mt * 16 + (lane >> 2)) * 20 + ks * 8 + (lane & 3)];
                    af[mt][0] = ap[0];
                    af[mt][1] = ap[8 * 20];
                    af[mt][2] = ap[4];
                    af[mt][3] = ap[8 * 20 + 4];
                }
#pragma unroll
                for (int nt = 0; nt < 4; nt++) {
                    const unsigned* bp = &smV[(wn + nt * 8 + (lane >> 2)) * VSTR + kc * 16 + ks * 8 + (lane & 3)];
                    bfr[nt][0] = bp[0];
                    bfr[nt][1] = bp[4];
                }
#pragma unroll
                for (int mt = 0; mt < 2; mt++)
#pragma unroll
                    for (int nt = 0; nt < 4; nt++)
                        asm volatile(
                            "mma.sync.aligned.m16n8k16.row.col.f32.bf16.bf16.f32 "
                            "{%0,%1,%2,%3}, {%4,%5,%6,%7}, {%8,%9}, {%0,%1,%2,%3};"
                            : "+f"(acc[mt][nt][0]), "+f"(acc[mt][nt][1]),
                              "+f"(acc[mt][nt][2]), "+f"(acc[mt][nt][3])
                            : "r"(af[mt][0]), "r"(af[mt][1]), "r"(af[mt][2]), "r"(af[mt][3]),
                              "r"(bfr[nt][0]), "r"(bfr[nt][1]));
            }
            if (kc + 1 < 32) {
                unsigned* Ad = smA + ((kc + 1) & 1) * (128 * 20);
                *(uint4*)&Ad[ldrow * 20 + kcol]        = a0;
                *(uint4*)&Ad[(ldrow + 64) * 20 + kcol] = a1;
            }
            __syncthreads();
        }

        // accum -> smem gate tile (overlays A staging; all mma reads done)
#pragma unroll
        for (int mt = 0; mt < 2; mt++) {
#pragma unroll
            for (int nt = 0; nt < 4; nt++) {
                int lr = wm + mt * 16 + (lane >> 2);
                int lc = wn + nt * 8 + (lane & 3) * 2;
                smG[lr * GS + lc]           = acc[mt][nt][0];
                smG[lr * GS + lc + 1]       = acc[mt][nt][1];
                smG[(lr + 8) * GS + lc]     = acc[mt][nt][2];
                smG[(lr + 8) * GS + lc + 1] = acc[mt][nt][3];
            }
        }
        __syncthreads();

        // fused LSTM cell (c in registers)
        unsigned* hbout = g_hb[(t & 1) ^ 1];
#pragma unroll
        for (int it = 0; it < 4; it++) {
            int idx = tid + it * PTHREADS;
            int lr = idx >> 3, jp = idx & 7;
            int m = m0 + lr;
            size_t zb = ((size_t)t * BATCH + m) * NG + n0 + jp * 8;
            float4 z0 = *(const float4*)&g_Zin[zb];
            float4 z1 = *(const float4*)&g_Zin[zb + 4];
            const float* Gp = &smG[lr * GS + jp * 8];

            float i0 = fsig(Gp[0] + z0.x);
            float f0 = fsig(Gp[1] + z0.y);
            float g0 = tanhf(Gp[2] + z0.z);
            float o0 = fsig(Gp[3] + z0.w);
            float i1 = fsig(Gp[4] + z1.x);
            float f1 = fsig(Gp[5] + z1.y);
            float g1 = tanhf(Gp[6] + z1.z);
            float o1 = fsig(Gp[7] + z1.w);

            float cn0 = f0 * creg[it][0] + i0 * g0;
            float cn1 = f1 * creg[it][1] + i1 * g1;
            creg[it][0] = cn0; creg[it][1] = cn1;

            float h0v = o0 * tanhf(cn0);
            float h1v = o1 * tanhf(cn1);
            hbout[m * 512 + nsl * 8 + jp] = pack_bf2(h0v, h1v);
            if (t == SEQL - 1) {
                float2 hf; hf.x = h0v; hf.y = h1v;
                *(float2*)&g_h[0][m * HIDN + nsl * 16 + jp * 2] = hf;
            }
        }

        // grid barrier between steps (not after the last one)
        if (t < SEQL - 1) {
            __syncthreads();
            if (tid == 0) {
                __threadfence();
                atomicAdd(&g_bar, 1u);
                const unsigned target = (unsigned)NCTA * (t + 1);
                unsigned v;
                do {
                    asm volatile("ld.acquire.gpu.u32 %0, [%1];"
                                 : "=r"(v) : "l"(&g_bar) : "memory");
                } while (v < target);
            }
            __syncthreads();
        }
    }
}

// ---------------- launch ----------------
extern "C" void kernel_launch(void* const* d_in, const int* in_sizes, int n_in,
                              void* d_out, int out_size)
{
    const int*   X   = (const int*)  d_in[0];
    const float* h0  = (const float*)d_in[1];
    const float* c0  = (const float*)d_in[2];
    const float* emb = (const float*)d_in[3];
    const float* Ui  = (const float*)d_in[4];
    const float* Vi  = (const float*)d_in[5];
    const float* bi  = (const float*)d_in[6];
    const float* Uf  = (const float*)d_in[7];
    const float* Vf  = (const float*)d_in[8];
    const float* bf  = (const float*)d_in[9];
    const float* Uc  = (const float*)d_in[10];
    const float* Vc  = (const float*)d_in[11];
    const float* bc  = (const float*)d_in[12];
    const float* Uo  = (const float*)d_in[13];
    const float* Vo  = (const float*)d_in[14];
    const float* bo  = (const float*)d_in[15];
    const float* W   = (const float*)d_in[16];
    const float* b   = (const float*)d_in[17];
    float* out = (float*)d_out;

    // allow >48KB dynamic smem for the persistent kernel (host-side, capture-safe)
    cudaFuncSetAttribute(lstm_persistent_kernel,
                         cudaFuncAttributeMaxDynamicSharedMemorySize, SMEM_P_BYTES);

    // 1) interleave weights (U fp32, V bf16), copy h0/c0, reset barrier
    pack_kernel<<<(NG * HIDN + 255) / 256, 256>>>(Ui, Vi, bi, Uf, Vf, bf,
                                                  Uc, Vc, bc, Uo, Vo, bo, h0, c0);

    // 2) all input-side gate preactivations (tf32, parallel over timesteps)
    gemm_kernel<0><<<dim3(NG / BN, (SEQL * BATCH) / BM), 128>>>(
        nullptr, X, emb, nullptr, nullptr, 0);

    // 3) all 128 recurrent steps in ONE persistent kernel (V resident in SMEM)
    lstm_persistent_kernel<<<NCTA, PTHREADS, SMEM_P_BYTES>>>();

    // 4) output projection: h_final (fp32, in g_h[0]) @ W^T + b
    gemm_kernel<2><<<dim3(NCLS / BN, BATCH / BM), 128>>>(
        W, nullptr, nullptr, b, out, SEQL);
}

// round 4
// speedup vs baseline: 2.4841x; 1.3557x over previous
#include <cuda_runtime.h>
#include <cuda_bf16.h>
#include <cstdint>
#include <cmath>

#define HIDN 1024
#define EMBD 1024
#define BATCH 256
#define SEQL 128
#define NCLS 32000
#define NG   4096   /* 4*HIDN, gate-interleaved: n = 4*j + g, g in {i,f,c,o} */

#define BM 128
#define BN 64
#define BK 16
#define AS 20
#define BSS 20
#define GS 68
#define VSTR 516

#define NCTA 128
#define PTHREADS 256

// ---------------- device scratch (no allocations allowed) ----------------
static __device__ unsigned g_Ub[NG * (HIDN / 2)];            // 8 MB interleaved U, bf16x2
static __device__ unsigned g_Vb[NG * (HIDN / 2)];            // 8 MB interleaved V, bf16x2
static __device__ unsigned g_Eb[(size_t)NCLS * (EMBD / 2)];  // 64 MB emb, bf16x2
static __device__ float    g_ball[NG];
static __device__ float    g_Zin[(size_t)SEQL * BATCH * NG]; // 512 MB input-side gates
static __device__ float    g_h[2][BATCH * HIDN];             // fp32 h (final proj reads [0])
static __device__ unsigned g_hb[2][BATCH * (HIDN / 2)];      // bf16x2 h ping-pong
static __device__ float    g_c[BATCH * HIDN];
static __device__ unsigned g_bar;                            // grid barrier (reset each replay)

// ---------------- helpers ----------------
__device__ __forceinline__ float f2tf32(float x) {
    uint32_t r;
    asm("cvt.rna.tf32.f32 %0, %1;" : "=r"(r) : "f"(x));
    return __uint_as_float(r);
}
__device__ __forceinline__ unsigned pack_bf2(float a, float b) {
    __nv_bfloat162 v = __floats2bfloat162_rn(a, b);
    return *reinterpret_cast<unsigned*>(&v);
}
__device__ __forceinline__ float fsig(float x) {
    return __fdividef(1.f, 1.f + __expf(-x));
}

// ---------------- pack: interleave U/V (bf16), biases, init state ----------------
__global__ void pack_kernel(const float* __restrict__ Ui, const float* __restrict__ Vi, const float* __restrict__ bi,
                            const float* __restrict__ Uf, const float* __restrict__ Vf, const float* __restrict__ bf,
                            const float* __restrict__ Uc, const float* __restrict__ Vc, const float* __restrict__ bc,
                            const float* __restrict__ Uo, const float* __restrict__ Vo, const float* __restrict__ bo,
                            const float* __restrict__ h0, const float* __restrict__ c0)
{
    int idx = blockIdx.x * blockDim.x + threadIdx.x;   // over NG * 512 half2 units
    if (idx >= NG * (HIDN / 2)) return;
    if (idx == 0) g_bar = 0u;
    int n = idx >> 9;           // gate-interleaved output row
    int k2 = idx & 511;         // half2 unit
    int j = n >> 2, g = n & 3;
    const float *U, *V, *bb;
    if (g == 0)      { U = Ui; V = Vi; bb = bi; }
    else if (g == 1) { U = Uf; V = Vf; bb = bf; }
    else if (g == 2) { U = Uc; V = Vc; bb = bc; }
    else             { U = Uo; V = Vo; bb = bo; }
    const float* Up = U + (size_t)j * HIDN + 2 * k2;
    const float* Vp = V + (size_t)j * HIDN + 2 * k2;
    g_Ub[idx] = pack_bf2(Up[0], Up[1]);
    g_Vb[idx] = pack_bf2(Vp[0], Vp[1]);
    if (k2 == 0) g_ball[n] = bb[j];
    if (idx < BATCH * (HIDN / 2)) {
        g_hb[0][idx] = pack_bf2(h0[2 * idx], h0[2 * idx + 1]);
        float2 hv; hv.x = h0[2 * idx]; hv.y = h0[2 * idx + 1];
        *(float2*)&g_h[0][2 * idx] = hv;
        float2 cv; cv.x = c0[2 * idx]; cv.y = c0[2 * idx + 1];
        *(float2*)&g_c[2 * idx] = cv;
    }
}

// ---------------- pack emb -> bf16 ----------------
__global__ void pack_emb_kernel(const float* __restrict__ emb)
{
    size_t idx = (size_t)blockIdx.x * blockDim.x + threadIdx.x; // over NCLS*512 half2
    if (idx >= (size_t)NCLS * (EMBD / 2)) return;
    g_Eb[idx] = pack_bf2(emb[2 * idx], emb[2 * idx + 1]);
}

// ---------------- bf16 input GEMM: Zin = gather(emb,X) @ Uall^T + ball ----------------
// grid (64, 256), 256 threads, tile 128x64, K=1024 (512 half2), chunk 16 half2
__global__ __launch_bounds__(256)
void input_gemm_kernel(const int* __restrict__ Xids)
{
    const int tid  = threadIdx.x;
    const int lane = tid & 31;
    const int warp = tid >> 5;
    const int wm = (warp >> 1) * 32;
    const int wn = (warp & 1) * 32;
    const int n0 = blockIdx.x * 64;
    const int m0 = blockIdx.y * 128;

    __shared__ unsigned smA[2][128 * 20];
    __shared__ unsigned smB[2][64 * 20];

    const int kcol  = (tid & 3) * 4;
    const int ldrow = tid >> 2;     // 0..63

    int r0 = m0 + ldrow, r1 = m0 + ldrow + 64;
    int v0 = Xids[(r0 & 255) * SEQL + (r0 >> 8)];
    int v1 = Xids[(r1 & 255) * SEQL + (r1 >> 8)];
    const unsigned* arp0 = g_Eb + (size_t)v0 * 512 + kcol;
    const unsigned* arp1 = g_Eb + (size_t)v1 * 512 + kcol;
    const unsigned* brp  = g_Ub + (size_t)(n0 + ldrow) * 512 + kcol;

    float acc[2][4][4];
#pragma unroll
    for (int a = 0; a < 2; a++)
#pragma unroll
        for (int b_ = 0; b_ < 4; b_++)
#pragma unroll
            for (int c_ = 0; c_ < 4; c_++) acc[a][b_][c_] = 0.f;

    uint4 a0 = *(const uint4*)arp0;
    uint4 a1 = *(const uint4*)arp1;
    uint4 b0 = *(const uint4*)brp;
    *(uint4*)&smA[0][ldrow * 20 + kcol]        = a0;
    *(uint4*)&smA[0][(ldrow + 64) * 20 + kcol] = a1;
    *(uint4*)&smB[0][ldrow * 20 + kcol]        = b0;
    __syncthreads();

    for (int kc = 0; kc < 32; kc++) {
        const int cur = kc & 1;
        if (kc + 1 < 32) {
            a0 = *(const uint4*)(arp0 + (kc + 1) * 16);
            a1 = *(const uint4*)(arp1 + (kc + 1) * 16);
            b0 = *(const uint4*)(brp  + (kc + 1) * 16);
        }
#pragma unroll
        for (int ks = 0; ks < 2; ks++) {
            unsigned af[2][4], bfr[4][2];
#pragma unroll
            for (int mt = 0; mt < 2; mt++) {
                const unsigned* ap = &smA[cur][(wm + mt * 16 + (lane >> 2)) * 20 + ks * 8 + (lane & 3)];
                af[mt][0] = ap[0];
                af[mt][1] = ap[8 * 20];
                af[mt][2] = ap[4];
                af[mt][3] = ap[8 * 20 + 4];
            }
#pragma unroll
            for (int nt = 0; nt < 4; nt++) {
                const unsigned* bp = &smB[cur][(wn + nt * 8 + (lane >> 2)) * 20 + ks * 8 + (lane & 3)];
                bfr[nt][0] = bp[0];
                bfr[nt][1] = bp[4];
            }
#pragma unroll
            for (int mt = 0; mt < 2; mt++)
#pragma unroll
                for (int nt = 0; nt < 4; nt++)
                    asm volatile(
                        "mma.sync.aligned.m16n8k16.row.col.f32.bf16.bf16.f32 "
                        "{%0,%1,%2,%3}, {%4,%5,%6,%7}, {%8,%9}, {%0,%1,%2,%3};"
                        : "+f"(acc[mt][nt][0]), "+f"(acc[mt][nt][1]),
                          "+f"(acc[mt][nt][2]), "+f"(acc[mt][nt][3])
                        : "r"(af[mt][0]), "r"(af[mt][1]), "r"(af[mt][2]), "r"(af[mt][3]),
                          "r"(bfr[nt][0]), "r"(bfr[nt][1]));
        }
        if (kc + 1 < 32) {
            const int nxt = (kc + 1) & 1;
            *(uint4*)&smA[nxt][ldrow * 20 + kcol]        = a0;
            *(uint4*)&smA[nxt][(ldrow + 64) * 20 + kcol] = a1;
            *(uint4*)&smB[nxt][ldrow * 20 + kcol]        = b0;
        }
        __syncthreads();
    }

    // epilogue: + bias, store fp32 Zin
#pragma unroll
    for (int mt = 0; mt < 2; mt++) {
#pragma unroll
        for (int nt = 0; nt < 4; nt++) {
            int r = m0 + wm + mt * 16 + (lane >> 2);
            int cidx = n0 + wn + nt * 8 + (lane & 3) * 2;
            float2 bv = *(const float2*)&g_ball[cidx];
            float2 o0; o0.x = acc[mt][nt][0] + bv.x; o0.y = acc[mt][nt][1] + bv.y;
            float2 o1; o1.x = acc[mt][nt][2] + bv.x; o1.y = acc[mt][nt][3] + bv.y;
            *(float2*)&g_Zin[(size_t)r * NG + cidx] = o0;
            *(float2*)&g_Zin[(size_t)(r + 8) * NG + cidx] = o1;
        }
    }
}

// ---------------- tf32 output projection: out = h_final @ W^T + b ----------------
__global__ __launch_bounds__(128)
void out_gemm_kernel(const float* __restrict__ W,
                     const float* __restrict__ biasp,
                     float* __restrict__ Cout)
{
    const int tid  = threadIdx.x;
    const int lane = tid & 31;
    const int warp = tid >> 5;
    const int wm = (warp >> 1) * 64;
    const int wn = (warp & 1) * 32;
    const int n0 = blockIdx.x * BN;
    const int m0 = blockIdx.y * BM;

    __shared__ struct { float A[2][BM * AS]; float B[2][BN * BSS]; } sm;

    const float* Ain = g_h[0];
    const int kcol  = (tid & 3) * 4;
    const int ldrow = tid >> 2;

    const float* arp[4];
#pragma unroll
    for (int i = 0; i < 4; i++)
        arp[i] = Ain + (size_t)(m0 + ldrow + 32 * i) * HIDN + kcol;
    const float* brp[2];
#pragma unroll
    for (int i = 0; i < 2; i++)
        brp[i] = W + (size_t)(n0 + ldrow + 32 * i) * HIDN + kcol;

    float4 areg[4], breg[2];
    float acc[4][4][4];
#pragma unroll
    for (int a = 0; a < 4; a++)
#pragma unroll
        for (int b_ = 0; b_ < 4; b_++)
#pragma unroll
            for (int c_ = 0; c_ < 4; c_++) acc[a][b_][c_] = 0.f;

#pragma unroll
    for (int i = 0; i < 4; i++) areg[i] = *(const float4*)(arp[i]);
#pragma unroll
    for (int i = 0; i < 2; i++) breg[i] = *(const float4*)(brp[i]);
#pragma unroll
    for (int i = 0; i < 4; i++) {
        float4 v = areg[i];
        v.x = f2tf32(v.x); v.y = f2tf32(v.y); v.z = f2tf32(v.z); v.w = f2tf32(v.w);
        *(float4*)&sm.A[0][(ldrow + 32 * i) * AS + kcol] = v;
    }
#pragma unroll
    for (int i = 0; i < 2; i++) {
        float4 v = breg[i];
        v.x = f2tf32(v.x); v.y = f2tf32(v.y); v.z = f2tf32(v.z); v.w = f2tf32(v.w);
        *(float4*)&sm.B[0][(ldrow + 32 * i) * BSS + kcol] = v;
    }
    __syncthreads();

    const int NCH = HIDN / BK;
    for (int kc = 0; kc < NCH; kc++) {
        int cur = kc & 1;
        if (kc + 1 < NCH) {
#pragma unroll
            for (int i = 0; i < 4; i++) areg[i] = *(const float4*)(arp[i] + (kc + 1) * BK);
#pragma unroll
            for (int i = 0; i < 2; i++) breg[i] = *(const float4*)(brp[i] + (kc + 1) * BK);
        }
#pragma unroll
        for (int k8 = 0; k8 < BK; k8 += 8) {
            uint32_t af[4][4], bfr[4][2];
#pragma unroll
            for (int mt = 0; mt < 4; mt++) {
                const float* ap = &sm.A[cur][(wm + mt * 16 + (lane >> 2)) * AS + k8 + (lane & 3)];
                af[mt][0] = __float_as_uint(ap[0]);
                af[mt][1] = __float_as_uint(ap[8 * AS]);
                af[mt][2] = __float_as_uint(ap[4]);
                af[mt][3] = __float_as_uint(ap[8 * AS + 4]);
            }
#pragma unroll
            for (int nt = 0; nt < 4; nt++) {
                const float* bp = &sm.B[cur][(wn + nt * 8 + (lane >> 2)) * BSS + k8 + (lane & 3)];
                bfr[nt][0] = __float_as_uint(bp[0]);
                bfr[nt][1] = __float_as_uint(bp[4]);
            }
#pragma unroll
            for (int mt = 0; mt < 4; mt++)
#pragma unroll
                for (int nt = 0; nt < 4; nt++)
                    asm volatile(
                        "mma.sync.aligned.m16n8k8.row.col.f32.tf32.tf32.f32 "
                        "{%0,%1,%2,%3}, {%4,%5,%6,%7}, {%8,%9}, {%0,%1,%2,%3};"
                        : "+f"(acc[mt][nt][0]), "+f"(acc[mt][nt][1]),
                          "+f"(acc[mt][nt][2]), "+f"(acc[mt][nt][3])
                        : "r"(af[mt][0]), "r"(af[mt][1]), "r"(af[mt][2]), "r"(af[mt][3]),
                          "r"(bfr[nt][0]), "r"(bfr[nt][1]));
        }
        if (kc + 1 < NCH) {
            int nxt = cur ^ 1;
#pragma unroll
            for (int i = 0; i < 4; i++) {
                float4 v = areg[i];
                v.x = f2tf32(v.x); v.y = f2tf32(v.y); v.z = f2tf32(v.z); v.w = f2tf32(v.w);
                *(float4*)&sm.A[nxt][(ldrow + 32 * i) * AS + kcol] = v;
            }
#pragma unroll
            for (int i = 0; i < 2; i++) {
                float4 v = breg[i];
                v.x = f2tf32(v.x); v.y = f2tf32(v.y); v.z = f2tf32(v.z); v.w = f2tf32(v.w);
                *(float4*)&sm.B[nxt][(ldrow + 32 * i) * BSS + kcol] = v;
            }
        }
        __syncthreads();
    }

#pragma unroll
    for (int mt = 0; mt < 4; mt++) {
#pragma unroll
        for (int nt = 0; nt < 4; nt++) {
            int r = m0 + wm + mt * 16 + (lane >> 2);
            int cidx = n0 + wn + nt * 8 + (lane & 3) * 2;
            float2 bv = *(const float2*)&biasp[cidx];
            float2 v0; v0.x = acc[mt][nt][0] + bv.x; v0.y = acc[mt][nt][1] + bv.y;
            float2 v1; v1.x = acc[mt][nt][2] + bv.x; v1.y = acc[mt][nt][3] + bv.y;
            *(float2*)&Cout[(size_t)r * NCLS + cidx] = v0;
            *(float2*)&Cout[(size_t)(r + 8) * NCLS + cidx] = v1;
        }
    }
}

// ---------------- persistent recurrent kernel ----------------
#define SMEM_V_BYTES   (64 * VSTR * 4)
#define SMEM_TAIL      (BM * GS * 4)
#define SMEM_P_BYTES   (SMEM_V_BYTES + SMEM_TAIL)

__global__ __launch_bounds__(PTHREADS, 1)
void lstm_persistent_kernel()
{
    extern __shared__ unsigned smem[];
    unsigned* smV = smem;
    unsigned* smA = smem + 64 * VSTR;
    float*    smG = (float*)(smem + 64 * VSTR);

    const int tid  = threadIdx.x;
    const int lane = tid & 31;
    const int warp = tid >> 5;
    const int wm = (warp >> 1) * 32;
    const int wn = (warp & 1) * 32;
    const int bid = blockIdx.x;
    const int m0  = (bid & 1) * 128;
    const int nsl = bid >> 1;
    const int n0  = nsl * 64;

    for (int i = tid; i < 64 * 128; i += PTHREADS) {
        int n = i >> 7, k4 = (i & 127) * 4;
        *(uint4*)&smV[n * VSTR + k4] = *(const uint4*)&g_Vb[(size_t)(n0 + n) * 512 + k4];
    }

    float creg[4][2];
#pragma unroll
    for (int it = 0; it < 4; it++) {
        int idx = tid + it * PTHREADS;
        int lr = idx >> 3, jp = idx & 7;
        float2 cv = *(const float2*)&g_c[(m0 + lr) * HIDN + nsl * 16 + jp * 2];
        creg[it][0] = cv.x; creg[it][1] = cv.y;
    }

    const int kcol  = (tid & 3) * 4;
    const int ldrow = tid >> 2;
    __syncthreads();

    for (int t = 0; t < SEQL; t++) {
        // prefetch this step's Zin slice early (MLP=8, hidden behind the GEMM)
        float4 zpre[4][2];
#pragma unroll
        for (int it = 0; it < 4; it++) {
            int idx = tid + it * PTHREADS;
            int lr = idx >> 3, jp = idx & 7;
            size_t zb = ((size_t)t * BATCH + m0 + lr) * NG + n0 + jp * 8;
            zpre[it][0] = *(const float4*)&g_Zin[zb];
            zpre[it][1] = *(const float4*)&g_Zin[zb + 4];
        }

        const unsigned* hin = g_hb[t & 1];
        const unsigned* arp0 = hin + (size_t)(m0 + ldrow) * 512 + kcol;
        const unsigned* arp1 = hin + (size_t)(m0 + ldrow + 64) * 512 + kcol;

        float acc[2][4][4];
#pragma unroll
        for (int a = 0; a < 2; a++)
#pragma unroll
            for (int b_ = 0; b_ < 4; b_++)
#pragma unroll
                for (int c_ = 0; c_ < 4; c_++) acc[a][b_][c_] = 0.f;

        uint4 a0 = *(const uint4*)arp0;
        uint4 a1 = *(const uint4*)arp1;
        *(uint4*)&smA[ldrow * 20 + kcol]        = a0;
        *(uint4*)&smA[(ldrow + 64) * 20 + kcol] = a1;
        __syncthreads();

        for (int kc = 0; kc < 32; kc++) {
            const int cur = kc & 1;
            if (kc + 1 < 32) {
                a0 = *(const uint4*)(arp0 + (kc + 1) * 16);
                a1 = *(const uint4*)(arp1 + (kc + 1) * 16);
            }
            const unsigned* As = smA + cur * (128 * 20);
#pragma unroll
            for (int ks = 0; ks < 2; ks++) {
                unsigned af[2][4], bfr[4][2];
#pragma unroll
                for (int mt = 0; mt < 2; mt++) {
                    const unsigned* ap = &As[(wm + mt * 16 + (lane >> 2)) * 20 + ks * 8 + (lane & 3)];
                    af[mt][0] = ap[0];
                    af[mt][1] = ap[8 * 20];
                    af[mt][2] = ap[4];
                    af[mt][3] = ap[8 * 20 + 4];
                }
#pragma unroll
                for (int nt = 0; nt < 4; nt++) {
                    const unsigned* bp = &smV[(wn + nt * 8 + (lane >> 2)) * VSTR + kc * 16 + ks * 8 + (lane & 3)];
                    bfr[nt][0] = bp[0];
                    bfr[nt][1] = bp[4];
                }
#pragma unroll
                for (int mt = 0; mt < 2; mt++)
#pragma unroll
                    for (int nt = 0; nt < 4; nt++)
                        asm volatile(
                            "mma.sync.aligned.m16n8k16.row.col.f32.bf16.bf16.f32 "
                            "{%0,%1,%2,%3}, {%4,%5,%6,%7}, {%8,%9}, {%0,%1,%2,%3};"
                            : "+f"(acc[mt][nt][0]), "+f"(acc[mt][nt][1]),
                              "+f"(acc[mt][nt][2]), "+f"(acc[mt][nt][3])
                            : "r"(af[mt][0]), "r"(af[mt][1]), "r"(af[mt][2]), "r"(af[mt][3]),
                              "r"(bfr[nt][0]), "r"(bfr[nt][1]));
            }
            if (kc + 1 < 32) {
                unsigned* Ad = smA + ((kc + 1) & 1) * (128 * 20);
                *(uint4*)&Ad[ldrow * 20 + kcol]        = a0;
                *(uint4*)&Ad[(ldrow + 64) * 20 + kcol] = a1;
            }
            __syncthreads();
        }

#pragma unroll
        for (int mt = 0; mt < 2; mt++) {
#pragma unroll
            for (int nt = 0; nt < 4; nt++) {
                int lr = wm + mt * 16 + (lane >> 2);
                int lc = wn + nt * 8 + (lane & 3) * 2;
                smG[lr * GS + lc]           = acc[mt][nt][0];
                smG[lr * GS + lc + 1]       = acc[mt][nt][1];
                smG[(lr + 8) * GS + lc]     = acc[mt][nt][2];
                smG[(lr + 8) * GS + lc + 1] = acc[mt][nt][3];
            }
        }
        __syncthreads();

        unsigned* hbout = g_hb[(t & 1) ^ 1];
#pragma unroll
        for (int it = 0; it < 4; it++) {
            int idx = tid + it * PTHREADS;
            int lr = idx >> 3, jp = idx & 7;
            int m = m0 + lr;
            float4 z0 = zpre[it][0];
            float4 z1 = zpre[it][1];
            const float* Gp = &smG[lr * GS + jp * 8];

            float i0 = fsig(Gp[0] + z0.x);
            float f0 = fsig(Gp[1] + z0.y);
            float g0 = tanhf(Gp[2] + z0.z);
            float o0 = fsig(Gp[3] + z0.w);
            float i1 = fsig(Gp[4] + z1.x);
            float f1 = fsig(Gp[5] + z1.y);
            float g1 = tanhf(Gp[6] + z1.z);
            float o1 = fsig(Gp[7] + z1.w);

            float cn0 = f0 * creg[it][0] + i0 * g0;
            float cn1 = f1 * creg[it][1] + i1 * g1;
            creg[it][0] = cn0; creg[it][1] = cn1;

            float h0v = o0 * tanhf(cn0);
            float h1v = o1 * tanhf(cn1);
            hbout[m * 512 + nsl * 8 + jp] = pack_bf2(h0v, h1v);
            if (t == SEQL - 1) {
                float2 hf; hf.x = h0v; hf.y = h1v;
                *(float2*)&g_h[0][m * HIDN + nsl * 16 + jp * 2] = hf;
            }
        }

        if (t < SEQL - 1) {
            __syncthreads();
            if (tid == 0) {
                __threadfence();
                atomicAdd(&g_bar, 1u);
                const unsigned target = (unsigned)NCTA * (t + 1);
                unsigned v;
                do {
                    asm volatile("ld.acquire.gpu.u32 %0, [%1];"
                                 : "=r"(v) : "l"(&g_bar) : "memory");
                } while (v < target);
            }
            __syncthreads();
        }
    }
}

// ---------------- launch ----------------
extern "C" void kernel_launch(void* const* d_in, const int* in_sizes, int n_in,
                              void* d_out, int out_size)
{
    const int*   X   = (const int*)  d_in[0];
    const float* h0  = (const float*)d_in[1];
    const float* c0  = (const float*)d_in[2];
    const float* emb = (const float*)d_in[3];
    const float* Ui  = (const float*)d_in[4];
    const float* Vi  = (const float*)d_in[5];
    const float* bi  = (const float*)d_in[6];
    const float* Uf  = (const float*)d_in[7];
    const float* Vf  = (const float*)d_in[8];
    const float* bf  = (const float*)d_in[9];
    const float* Uc  = (const float*)d_in[10];
    const float* Vc  = (const float*)d_in[11];
    const float* bc  = (const float*)d_in[12];
    const float* Uo  = (const float*)d_in[13];
    const float* Vo  = (const float*)d_in[14];
    const float* bo  = (const float*)d_in[15];
    const float* W   = (const float*)d_in[16];
    const float* b   = (const float*)d_in[17];
    float* out = (float*)d_out;

    cudaFuncSetAttribute(lstm_persistent_kernel,
                         cudaFuncAttributeMaxDynamicSharedMemorySize, SMEM_P_BYTES);

    // 1) pack weights to bf16 (interleaved), biases, init state, reset barrier
    pack_kernel<<<(NG * (HIDN / 2) + 255) / 256, 256>>>(Ui, Vi, bi, Uf, Vf, bf,
                                                        Uc, Vc, bc, Uo, Vo, bo, h0, c0);
    pack_emb_kernel<<<(int)(((size_t)NCLS * (EMBD / 2) + 255) / 256), 256>>>(emb);

    // 2) all input-side gate preactivations (bf16 tensor cores)
    input_gemm_kernel<<<dim3(NG / 64, (SEQL * BATCH) / 128), 256>>>(X);

    // 3) all 128 recurrent steps in ONE persistent kernel (V resident in SMEM)
    lstm_persistent_kernel<<<NCTA, PTHREADS, SMEM_P_BYTES>>>();

    // 4) output projection (tf32): out = h_final @ W^T + b
    out_gemm_kernel<<<dim3(NCLS / BN, BATCH / BM), 128>>>(W, b, out);
}